// round 1
// baseline (speedup 1.0000x reference)
#include <cuda_runtime.h>

#define C_DIM   1024
#define DFF     4096
#define NTOK    16384
#define NEXP    4
#define TILE_FF 1024   // DFF / NEXP
#define TILE_C  256    // C / NEXP

#define BM 128
#define BN 128
#define BK 8

// ---- device scratch (no allocations allowed) ----
__device__ int   g_cnt[NEXP];
__device__ int   g_perm[NEXP * NTOK];
__device__ float g_hidden[(size_t)NTOK * TILE_FF];   // 64 MB

__global__ void init_kernel() {
    if (threadIdx.x < NEXP) g_cnt[threadIdx.x] = 0;
}

// One warp per token: logits = x . Wg^T + bg, argmax -> one-hot gate, bucket token.
__global__ void gate_kernel(const float* __restrict__ x,
                            const float* __restrict__ Wg,
                            const float* __restrict__ bg,
                            float* __restrict__ gate_out) {
    int warp = (blockIdx.x * blockDim.x + threadIdx.x) >> 5;
    int lane = threadIdx.x & 31;
    if (warp >= NTOK) return;
    const float* xr = x + (size_t)warp * C_DIM;

    float acc[NEXP] = {0.f, 0.f, 0.f, 0.f};
    for (int k = lane; k < C_DIM; k += 32) {
        float xv = xr[k];
#pragma unroll
        for (int e = 0; e < NEXP; e++) acc[e] += xv * Wg[e * C_DIM + k];
    }
#pragma unroll
    for (int e = 0; e < NEXP; e++) {
#pragma unroll
        for (int off = 16; off; off >>= 1)
            acc[e] += __shfl_xor_sync(0xffffffffu, acc[e], off);
    }
    // all lanes now hold full sums
    int best = 0;
    float bv = acc[0] + bg[0];
#pragma unroll
    for (int e = 1; e < NEXP; e++) {
        float v = acc[e] + bg[e];
        if (v > bv) { bv = v; best = e; }   // strict > keeps first index on ties (argmax semantics)
    }
    if (gate_out != nullptr && lane < NEXP)
        gate_out[(size_t)warp * NEXP + lane] = (lane == best) ? 1.0f : 0.0f;
    if (lane == 0) {
        int pos = atomicAdd(&g_cnt[best], 1);
        g_perm[best * NTOK + pos] = warp;
    }
}

// MODE 1: H = relu(X_e @ W_up_e^T + b_up)   (A = x,        out = g_hidden)
// MODE 2: out_tile = H @ W_down_tile^T + bd (A = g_hidden, out = d_out, scattered)
template <int MODE>
__global__ __launch_bounds__(256, 2)
void gemm_kernel(const float* __restrict__ A,
                 const float* __restrict__ W,
                 const float* __restrict__ bias,
                 float* __restrict__ out) {
    const int e   = blockIdx.z;
    const int cnt = g_cnt[e];
    const int m0  = blockIdx.x * BM;
    if (m0 >= cnt) return;
    const int nb = blockIdx.y * BN;          // local output-column block within expert
    const int K  = 1024;                     // both GEMMs have K = 1024
    const int NK = K / BK;

    const float* Abase = (MODE == 1) ? A : g_hidden;
    const float* Wbase;
    int ldw;
    if (MODE == 1) { Wbase = W + (size_t)(e * TILE_FF + nb) * C_DIM;              ldw = C_DIM; }
    else           { Wbase = W + (size_t)(e * TILE_C + nb) * DFF + e * TILE_FF;   ldw = DFF;   }

    __shared__ float As[2][BK][BM];
    __shared__ float Bs[2][BK][BN];

    const int tid  = threadIdx.x;
    const int aRow = tid >> 1;          // 0..127
    const int aCol = (tid & 1) * 4;     // 0 or 4

    const int  gm     = m0 + aRow;
    const bool aValid = gm < cnt;
    const float* pA = nullptr;
    if (aValid) {
        int grow = g_perm[e * NTOK + gm];
        pA = Abase + (size_t)grow * 1024 + aCol;
    }
    const float* pB = Wbase + (size_t)aRow * ldw + aCol;

    const int tx = tid & 15, ty = tid >> 4;

    float acc[8][8];
#pragma unroll
    for (int i = 0; i < 8; i++)
#pragma unroll
        for (int j = 0; j < 8; j++) acc[i][j] = 0.f;

    // prologue: stage 0
    float4 a0 = aValid ? *(const float4*)pA : make_float4(0.f, 0.f, 0.f, 0.f);
    float4 b0 = *(const float4*)pB;
    As[0][aCol + 0][aRow] = a0.x; As[0][aCol + 1][aRow] = a0.y;
    As[0][aCol + 2][aRow] = a0.z; As[0][aCol + 3][aRow] = a0.w;
    Bs[0][aCol + 0][aRow] = b0.x; Bs[0][aCol + 1][aRow] = b0.y;
    Bs[0][aCol + 2][aRow] = b0.z; Bs[0][aCol + 3][aRow] = b0.w;
    __syncthreads();

    int buf = 0;
    for (int kt = 0; kt < NK; ++kt) {
        float4 an = make_float4(0.f, 0.f, 0.f, 0.f), bn;
        const bool pf = (kt + 1 < NK);
        if (pf) {
            const int koff = (kt + 1) * BK;
            if (aValid) an = *(const float4*)(pA + koff);
            bn = *(const float4*)(pB + koff);
        }
#pragma unroll
        for (int k = 0; k < BK; k++) {
            float ar[8], br[8];
            *(float4*)&ar[0] = *(const float4*)&As[buf][k][ty * 8];
            *(float4*)&ar[4] = *(const float4*)&As[buf][k][ty * 8 + 4];
            *(float4*)&br[0] = *(const float4*)&Bs[buf][k][tx * 8];
            *(float4*)&br[4] = *(const float4*)&Bs[buf][k][tx * 8 + 4];
#pragma unroll
            for (int i = 0; i < 8; i++)
#pragma unroll
                for (int j = 0; j < 8; j++) acc[i][j] += ar[i] * br[j];
        }
        if (pf) {
            const int nbuf = buf ^ 1;
            As[nbuf][aCol + 0][aRow] = an.x; As[nbuf][aCol + 1][aRow] = an.y;
            As[nbuf][aCol + 2][aRow] = an.z; As[nbuf][aCol + 3][aRow] = an.w;
            Bs[nbuf][aCol + 0][aRow] = bn.x; Bs[nbuf][aCol + 1][aRow] = bn.y;
            Bs[nbuf][aCol + 2][aRow] = bn.z; Bs[nbuf][aCol + 3][aRow] = bn.w;
            __syncthreads();
            buf = nbuf;
        }
    }

    // epilogue
    float bv[8];
#pragma unroll
    for (int j = 0; j < 8; j++) {
        int col = nb + tx * 8 + j;
        bv[j] = (MODE == 1) ? bias[e * TILE_FF + col] : bias[e * TILE_C + col];
    }
#pragma unroll
    for (int i = 0; i < 8; i++) {
        const int m = m0 + ty * 8 + i;
        if (m >= cnt) break;
        const int grow = g_perm[e * NTOK + m];
        float v[8];
#pragma unroll
        for (int j = 0; j < 8; j++) {
            float t = acc[i][j] + bv[j];
            v[j] = (MODE == 1) ? (t > 0.f ? t : 0.f) : t;
        }
        float* o;
        if (MODE == 1) o = g_hidden + (size_t)grow * TILE_FF + nb + tx * 8;
        else           o = out + (size_t)grow * C_DIM + e * TILE_C + nb + tx * 8;
        *(float4*)(o)     = make_float4(v[0], v[1], v[2], v[3]);
        *(float4*)(o + 4) = make_float4(v[4], v[5], v[6], v[7]);
    }
}

extern "C" void kernel_launch(void* const* d_in, const int* in_sizes, int n_in,
                              void* d_out, int out_size) {
    const float* x  = (const float*)d_in[0];
    const float* Wg = (const float*)d_in[1];
    const float* bg = (const float*)d_in[2];
    const float* Wu = (const float*)d_in[3];
    const float* bu = (const float*)d_in[4];
    const float* Wd = (const float*)d_in[5];
    const float* bd = (const float*)d_in[6];
    float* out = (float*)d_out;
    // Harness flattens (out, gate) in order: out [N*C] floats, then gate [N*4].
    float* gate_out = ((size_t)out_size > (size_t)NTOK * C_DIM)
                          ? out + (size_t)NTOK * C_DIM : nullptr;

    init_kernel<<<1, 32>>>();
    cudaMemsetAsync(out, 0, (size_t)NTOK * C_DIM * sizeof(float), 0);

    // gate: 1 warp per token -> 16384 warps
    gate_kernel<<<(NTOK * 32 + 255) / 256, 256>>>(x, Wg, bg, gate_out);

    dim3 g1(NTOK / BM, TILE_FF / BN, NEXP);   // (128, 8, 4)
    gemm_kernel<1><<<g1, 256>>>(x, Wu, bu, nullptr);

    dim3 g2(NTOK / BM, TILE_C / BN, NEXP);    // (128, 2, 4)
    gemm_kernel<2><<<g2, 256>>>(x, Wd, bd, out);
}

// round 6
// speedup vs baseline: 2.1635x; 2.1635x over previous
#include <cuda_runtime.h>
#include <cuda_bf16.h>
#include <cstdint>

#define C_DIM   1024
#define DFF     4096
#define NTOK    16384
#define NEXP    4
#define TILE_FF 1024
#define TILE_C  256

#define BM  128
#define BN  128
#define BK  32
#define NKI (1024 / BK)        // 32 K-chunks (both GEMMs have K=1024)

#define ROWB    80                      // padded smem row: 32 bf16 = 64B data + 16B pad
#define TILE_B  (128 * ROWB)            // 10240 B per operand tile
#define STAGE_B (4 * TILE_B)            // Ahi, Alo, Bhi, Blo
#define SMEM_B  (2 * STAGE_B)           // 81920 B double-buffered

// ---------------- device scratch (no allocations allowed) ----------------
__device__ int   g_cnt[NEXP];
__device__ int   g_perm[NEXP * NTOK];
__device__ __nv_bfloat16 g_xhi[(size_t)NTOK * C_DIM];
__device__ __nv_bfloat16 g_xlo[(size_t)NTOK * C_DIM];
__device__ __nv_bfloat16 g_wuphi[(size_t)DFF * C_DIM];
__device__ __nv_bfloat16 g_wuplo[(size_t)DFF * C_DIM];
__device__ __nv_bfloat16 g_wdnhi[(size_t)C_DIM * DFF];
__device__ __nv_bfloat16 g_wdnlo[(size_t)C_DIM * DFF];
__device__ __nv_bfloat16 g_hhi[(size_t)NTOK * TILE_FF];
__device__ __nv_bfloat16 g_hlo[(size_t)NTOK * TILE_FF];

// ---------------- helpers ----------------
__device__ __forceinline__ uint32_t smem_u32(const void* p) {
    uint32_t a;
    asm("{ .reg .u64 t; cvta.to.shared.u64 t, %1; cvt.u32.u64 %0, t; }" : "=r"(a) : "l"(p));
    return a;
}
__device__ __forceinline__ void ldsm4(uint32_t* r, uint32_t addr) {
    asm volatile("ldmatrix.sync.aligned.m8n8.x4.shared.b16 {%0,%1,%2,%3}, [%4];"
                 : "=r"(r[0]), "=r"(r[1]), "=r"(r[2]), "=r"(r[3]) : "r"(addr));
}
__device__ __forceinline__ void mma16816(float* c, const uint32_t* a, uint32_t b0, uint32_t b1) {
    asm volatile("mma.sync.aligned.m16n8k16.row.col.f32.bf16.bf16.f32 "
                 "{%0,%1,%2,%3}, {%4,%5,%6,%7}, {%8,%9}, {%0,%1,%2,%3};"
                 : "+f"(c[0]), "+f"(c[1]), "+f"(c[2]), "+f"(c[3])
                 : "r"(a[0]), "r"(a[1]), "r"(a[2]), "r"(a[3]), "r"(b0), "r"(b1));
}
#define CP16(dst, src) \
    asm volatile("cp.async.cg.shared.global [%0], [%1], 16;" :: "r"(dst), "l"(src) : "memory")
#define CP_COMMIT() asm volatile("cp.async.commit_group;" ::: "memory")

// ---------------- small kernels ----------------
__global__ void init_kernel() {
    if (threadIdx.x < NEXP) g_cnt[threadIdx.x] = 0;
}

__global__ void gate_kernel(const float* __restrict__ x, const float* __restrict__ Wg,
                            const float* __restrict__ bg, float* __restrict__ gate_out) {
    int warp = (blockIdx.x * blockDim.x + threadIdx.x) >> 5;
    int lane = threadIdx.x & 31;
    if (warp >= NTOK) return;
    const float* xr = x + (size_t)warp * C_DIM;
    float acc[NEXP] = {0.f, 0.f, 0.f, 0.f};
    for (int k = lane; k < C_DIM; k += 32) {
        float xv = xr[k];
#pragma unroll
        for (int e = 0; e < NEXP; e++) acc[e] += xv * Wg[e * C_DIM + k];
    }
#pragma unroll
    for (int e = 0; e < NEXP; e++) {
#pragma unroll
        for (int off = 16; off; off >>= 1) acc[e] += __shfl_xor_sync(0xffffffffu, acc[e], off);
    }
    int best = 0;
    float bv = acc[0] + bg[0];
#pragma unroll
    for (int e = 1; e < NEXP; e++) {
        float v = acc[e] + bg[e];
        if (v > bv) { bv = v; best = e; }
    }
    if (gate_out != nullptr && lane < NEXP)
        gate_out[(size_t)warp * NEXP + lane] = (lane == best) ? 1.0f : 0.0f;
    if (lane == 0) {
        int pos = atomicAdd(&g_cnt[best], 1);
        g_perm[best * NTOK + pos] = warp;
    }
}

__global__ void split_kernel(const float* __restrict__ s, __nv_bfloat16* __restrict__ hi,
                             __nv_bfloat16* __restrict__ lo, int n4) {
    int i = blockIdx.x * blockDim.x + threadIdx.x;
    if (i >= n4) return;
    float4 v = ((const float4*)s)[i];
    __nv_bfloat162 h01, h23, l01, l23;
    h01.x = __float2bfloat16(v.x); l01.x = __float2bfloat16(v.x - __bfloat162float(h01.x));
    h01.y = __float2bfloat16(v.y); l01.y = __float2bfloat16(v.y - __bfloat162float(h01.y));
    h23.x = __float2bfloat16(v.z); l23.x = __float2bfloat16(v.z - __bfloat162float(h23.x));
    h23.y = __float2bfloat16(v.w); l23.y = __float2bfloat16(v.w - __bfloat162float(h23.y));
    ((__nv_bfloat162*)hi)[2 * i]     = h01;
    ((__nv_bfloat162*)hi)[2 * i + 1] = h23;
    ((__nv_bfloat162*)lo)[2 * i]     = l01;
    ((__nv_bfloat162*)lo)[2 * i + 1] = l23;
}

// ---------------- HMMA split-bf16 GEMM ----------------
// MODE 1: H = relu(X_e @ Wup_e^T + bu)  -> g_hhi/g_hlo (by token row)
// MODE 2: out_tile = H @ Wdn_tile^T + bd -> d_out (scattered fp32)
template <int MODE>
__global__ __launch_bounds__(256, 1)
void gemm_tc(const __nv_bfloat16* __restrict__ Ahi, const __nv_bfloat16* __restrict__ Alo,
             const __nv_bfloat16* __restrict__ Whi, const __nv_bfloat16* __restrict__ Wlo,
             const float* __restrict__ bias, float* __restrict__ out) {
    extern __shared__ char smem[];
    const int e   = blockIdx.z;
    const int cnt = g_cnt[e];
    const int m0  = blockIdx.x * BM;
    if (m0 >= cnt) return;
    const int nb  = blockIdx.y * BN;
    const int ldk = (MODE == 1) ? C_DIM : DFF;

    const uint32_t sb = smem_u32(smem);
    const int tid = threadIdx.x, lane = tid & 31, wid = tid >> 5;
    const int wm = wid & 1, wn = wid >> 1;      // warp tile (wm*64, wn*32)

    // ---- per-thread staging pointers (thread t -> row t>>1, chunk pair (t&1)*2) ----
    const int lrow = tid >> 1;
    const int gm   = m0 + lrow;
    const int grow0 = (gm < cnt) ? g_perm[e * NTOK + gm] : g_perm[e * NTOK];
    const __nv_bfloat16* pAhi = Ahi + (size_t)grow0 * 1024;
    const __nv_bfloat16* pAlo = Alo + (size_t)grow0 * 1024;
    size_t wr = (MODE == 1) ? (size_t)(e * TILE_FF + nb + lrow) * C_DIM
                            : (size_t)(e * TILE_C + nb + lrow) * DFF + (size_t)e * TILE_FF;
    const __nv_bfloat16* pWhi = Whi + wr;
    const __nv_bfloat16* pWlo = Wlo + wr;
    const int c0 = (tid & 1) * 2;
    const uint32_t drow = (uint32_t)lrow * ROWB;

#define LOAD_STAGE(kt) do {                                                       \
        const int _k0 = (kt) * BK;                                                \
        const uint32_t _st = sb + ((kt) & 1) * STAGE_B;                           \
        _Pragma("unroll")                                                         \
        for (int c = c0; c < c0 + 2; c++) {                                       \
            uint32_t d = _st + drow + c * 16;                                     \
            CP16(d,              pAhi + _k0 + c * 8);                             \
            CP16(d + TILE_B,     pAlo + _k0 + c * 8);                             \
            CP16(d + 2 * TILE_B, pWhi + _k0 + c * 8);                             \
            CP16(d + 3 * TILE_B, pWlo + _k0 + c * 8);                             \
        }                                                                         \
        CP_COMMIT();                                                              \
    } while (0)

    // ---- ldmatrix lane offsets ----
    const int sub = lane >> 3, r8 = lane & 7;
    const uint32_t aoff = (uint32_t)((((sub & 1) * 8 + r8) * ROWB) + ((sub >> 1) & 1) * 16);
    const uint32_t boff = (uint32_t)(((((sub & 2) ? 8 : 0) + r8) * ROWB) + (sub & 1) * 16);

    float acc[4][4][4];
#pragma unroll
    for (int i = 0; i < 4; i++)
#pragma unroll
        for (int j = 0; j < 4; j++)
#pragma unroll
            for (int k = 0; k < 4; k++) acc[i][j][k] = 0.f;

    LOAD_STAGE(0);
    for (int kt = 0; kt < NKI; kt++) {
        if (kt + 1 < NKI) {
            LOAD_STAGE(kt + 1);
            asm volatile("cp.async.wait_group 1;" ::: "memory");
        } else {
            asm volatile("cp.async.wait_group 0;" ::: "memory");
        }
        __syncthreads();

        const uint32_t st  = sb + (kt & 1) * STAGE_B;
        const uint32_t abA = st + (uint32_t)(wm * 64) * ROWB;
        const uint32_t bbB = st + 2 * TILE_B + (uint32_t)(wn * 32) * ROWB;
#pragma unroll
        for (int h = 0; h < 2; h++) {
            uint32_t ah[4][4], al[4][4], bh[2][4], bl[2][4];
#pragma unroll
            for (int mi = 0; mi < 4; mi++) {
                uint32_t a = abA + (uint32_t)(mi * 16) * ROWB + h * 32 + aoff;
                ldsm4(ah[mi], a);
                ldsm4(al[mi], a + TILE_B);
            }
#pragma unroll
            for (int nt = 0; nt < 2; nt++) {
                uint32_t b = bbB + (uint32_t)(nt * 16) * ROWB + h * 32 + boff;
                ldsm4(bh[nt], b);
                ldsm4(bl[nt], b + TILE_B);
            }
#pragma unroll
            for (int mi = 0; mi < 4; mi++)
#pragma unroll
                for (int nj = 0; nj < 4; nj++) {
                    const int nt = nj >> 1, p = (nj & 1) * 2;
                    mma16816(acc[mi][nj], ah[mi], bh[nt][p], bh[nt][p + 1]);
                    mma16816(acc[mi][nj], ah[mi], bl[nt][p], bl[nt][p + 1]);
                    mma16816(acc[mi][nj], al[mi], bh[nt][p], bh[nt][p + 1]);
                }
        }
        __syncthreads();
    }
#undef LOAD_STAGE

    // ---- epilogue ----
    const int qr = lane >> 2, qc = (lane & 3) * 2;
    float bv0[4], bv1[4];
#pragma unroll
    for (int nj = 0; nj < 4; nj++) {
        int cl = nb + wn * 32 + nj * 8 + qc;
        int bb = (MODE == 1) ? e * TILE_FF : e * TILE_C;
        bv0[nj] = bias[bb + cl];
        bv1[nj] = bias[bb + cl + 1];
    }
#pragma unroll
    for (int mi = 0; mi < 4; mi++) {
#pragma unroll
        for (int hh = 0; hh < 2; hh++) {
            const int m = m0 + wm * 64 + mi * 16 + hh * 8 + qr;
            if (m >= cnt) continue;
            const int grow = g_perm[e * NTOK + m];
#pragma unroll
            for (int nj = 0; nj < 4; nj++) {
                const int cl = nb + wn * 32 + nj * 8 + qc;
                float t0 = acc[mi][nj][hh * 2 + 0] + bv0[nj];
                float t1 = acc[mi][nj][hh * 2 + 1] + bv1[nj];
                if (MODE == 1) {
                    t0 = t0 > 0.f ? t0 : 0.f;
                    t1 = t1 > 0.f ? t1 : 0.f;
                    __nv_bfloat162 h, l;
                    h.x = __float2bfloat16(t0); l.x = __float2bfloat16(t0 - __bfloat162float(h.x));
                    h.y = __float2bfloat16(t1); l.y = __float2bfloat16(t1 - __bfloat162float(h.y));
                    *(__nv_bfloat162*)(g_hhi + (size_t)grow * TILE_FF + cl) = h;
                    *(__nv_bfloat162*)(g_hlo + (size_t)grow * TILE_FF + cl) = l;
                } else {
                    float2 v = make_float2(t0, t1);
                    *(float2*)(out + (size_t)grow * C_DIM + e * TILE_C + cl) = v;
                }
            }
        }
    }
}

// ---------------- launch ----------------
extern "C" void kernel_launch(void* const* d_in, const int* in_sizes, int n_in,
                              void* d_out, int out_size) {
    const float* x  = (const float*)d_in[0];
    const float* Wg = (const float*)d_in[1];
    const float* bg = (const float*)d_in[2];
    const float* Wu = (const float*)d_in[3];
    const float* bu = (const float*)d_in[4];
    const float* Wd = (const float*)d_in[5];
    const float* bd = (const float*)d_in[6];
    float* out = (float*)d_out;
    float* gate_out = ((size_t)out_size > (size_t)NTOK * C_DIM)
                          ? out + (size_t)NTOK * C_DIM : nullptr;

    cudaFuncSetAttribute(gemm_tc<1>, cudaFuncAttributeMaxDynamicSharedMemorySize, SMEM_B);
    cudaFuncSetAttribute(gemm_tc<2>, cudaFuncAttributeMaxDynamicSharedMemorySize, SMEM_B);

    __nv_bfloat16 *xhi, *xlo, *wuh, *wul, *wdh, *wdl, *hhi, *hlo;
    cudaGetSymbolAddress((void**)&xhi, g_xhi);
    cudaGetSymbolAddress((void**)&xlo, g_xlo);
    cudaGetSymbolAddress((void**)&wuh, g_wuphi);
    cudaGetSymbolAddress((void**)&wul, g_wuplo);
    cudaGetSymbolAddress((void**)&wdh, g_wdnhi);
    cudaGetSymbolAddress((void**)&wdl, g_wdnlo);
    cudaGetSymbolAddress((void**)&hhi, g_hhi);
    cudaGetSymbolAddress((void**)&hlo, g_hlo);

    init_kernel<<<1, 32>>>();
    cudaMemsetAsync(out, 0, (size_t)NTOK * C_DIM * sizeof(float), 0);

    gate_kernel<<<(NTOK * 32 + 255) / 256, 256>>>(x, Wg, bg, gate_out);

    split_kernel<<<(NTOK * C_DIM / 4 + 255) / 256, 256>>>(x,  xhi, xlo, NTOK * C_DIM / 4);
    split_kernel<<<(DFF * C_DIM / 4 + 255) / 256, 256>>>(Wu, wuh, wul, DFF * C_DIM / 4);
    split_kernel<<<(C_DIM * DFF / 4 + 255) / 256, 256>>>(Wd, wdh, wdl, C_DIM * DFF / 4);

    dim3 g1(NTOK / BM, TILE_FF / BN, NEXP);   // (128, 8, 4)
    gemm_tc<1><<<g1, 256, SMEM_B>>>(xhi, xlo, wuh, wul, bu, nullptr);

    dim3 g2(NTOK / BM, TILE_C / BN, NEXP);    // (128, 2, 4)
    gemm_tc<2><<<g2, 256, SMEM_B>>>(hhi, hlo, wdh, wdl, bd, out);
}